// round 7
// baseline (speedup 1.0000x reference)
#include <cuda_runtime.h>
#include <cuda_bf16.h>
#include <cstdint>

// ---------------------------------------------------------------------------
// FullyConnectedTensorProduct: 128x0e+128x1o+128x2e (x) 1x0e+1x1o+1x2e
//                              -> 128x0e+128x1o+128x2e, B = 32768
// Inputs (metadata order): x1 [B,1152] f32, x2 [B,9] f32, ws [11,128,1,128] f32
// Output: [B,1152] f32
//
// Factorization (MUL2 = 1):
//   G_p[i][k]   = sum_j C_p[i,j,k] * x2[b,j]               (tiny)
//   A_p[u][k]   = sum_i x1[b,u,i] * G_p[i][k]              (~2.5% of FLOPs)
//   out_p[w][k]+= sum_u ws[p][u][w] * A_p[u][k]            (dominant, FFMA2)
// sqrt(alpha_p)/||C_p||_F folded into C_p on device (fp64, exact reference math).
//
// Path table p : (l1,l2,lo)
//  0:(0,0,0) 1:(0,1,1) 2:(0,2,2) 3:(1,0,1) 4:(1,1,0) 5:(1,1,2)
//  6:(1,2,1) 7:(2,0,2) 8:(2,1,1) 9:(2,2,0) 10:(2,2,2)
// ---------------------------------------------------------------------------

#define TB 16         // batches per block (2 per warp, 8 warps)
#define KC 16         // u-chunk size
#define NTHREADS 256
#define ASTR 44       // sA row stride in float2 (padded; 44*8 = 352 B, 16B-aligned)

typedef unsigned long long u64;

// Device-side path tables (runtime-indexed -> must be __constant__, not
// namespace-scope constexpr, which has no device linkage).
__constant__ int c_l1[11]   = {0,0,0,1,1,1,1,2,2,2,2};
__constant__ int c_l2[11]   = {0,1,2,0,1,1,2,0,1,2,2};
__constant__ int c_lo[11]   = {0,1,2,1,0,2,1,2,1,0,2};
__constant__ int c_goff[11] = {0,1,4,9,18,21,36,45,70,85,90};   // prefix of (2l1+1)*(2lo+1)
// padded A offsets: NK=5 paths at 0,6,12,18; NK=3 at 24,28,32,36; NK=1 at 40,41,42
__constant__ int c_aoff[11] = {40,24,0,28,41,6,32,12,36,42,18};
__constant__ int c_s1off[3] = {0,128,512};
__constant__ int c_s2off[3] = {0,1,4};

// Scaled Wigner-3j tensors: g_W3[p][i][j][k], padded 5x5x5, pre-multiplied by
// sqrt(alpha_p)/frobenius_norm.
__device__ float g_W3[11 * 125];

// ---------------------------------------------------------------------------
// Init kernel: real Wigner-3j exactly as the reference (fp64).
// ---------------------------------------------------------------------------
__device__ __forceinline__ double dfact(int n) {
    double r = 1.0;
    for (int i = 2; i <= n; i++) r *= (double)i;
    return r;
}

__global__ void tp_init_w3() {
    int p = threadIdx.x;
    if (p >= 11) return;
    const int l1 = c_l1[p], l2 = c_l2[p], l3 = c_lo[p];

    // --- SU(2) Clebsch-Gordan ---
    double C[5][5][5];
    for (int a = 0; a < 5; a++)
        for (int b = 0; b < 5; b++)
            for (int c = 0; c < 5; c++) C[a][b][c] = 0.0;

    for (int m1 = -l1; m1 <= l1; m1++) {
        for (int m2 = -l2; m2 <= l2; m2++) {
            int m3 = m1 + m2;
            if (m3 < -l3 || m3 > l3) continue;
            double pref = sqrt((double)(2 * l3 + 1) * dfact(l3 + l1 - l2) * dfact(l3 - l1 + l2) *
                               dfact(l1 + l2 - l3) / dfact(l1 + l2 + l3 + 1));
            pref *= sqrt(dfact(l3 + m3) * dfact(l3 - m3) * dfact(l1 - m1) * dfact(l1 + m1) *
                         dfact(l2 - m2) * dfact(l2 + m2));
            double s = 0.0;
            for (int k = 0; k <= l1 + l2 - l3; k++) {
                if (l1 - m1 - k < 0 || l2 + m2 - k < 0 ||
                    l3 - l2 + m1 + k < 0 || l3 - l1 - m2 + k < 0) continue;
                double term = 1.0 / (dfact(k) * dfact(l1 + l2 - l3 - k) * dfact(l1 - m1 - k) *
                                     dfact(l2 + m2 - k) * dfact(l3 - l2 + m1 + k) *
                                     dfact(l3 - l1 - m2 + k));
                s += (k & 1) ? -term : term;
            }
            C[l1 + m1][l2 + m2][l3 + m3] = pref * s;
        }
    }

    // --- real-basis matrices q(l) = (-i)^l * base (e3nn convention) ---
    double Qr[3][5][5], Qi[3][5][5];
    int ls[3] = {l1, l2, l3};
    for (int t = 0; t < 3; t++) {
        int l = ls[t];
        for (int a = 0; a < 5; a++)
            for (int b = 0; b < 5; b++) { Qr[t][a][b] = 0.0; Qi[t][a][b] = 0.0; }
        double inv = 1.0 / sqrt(2.0);
        for (int m = -l; m < 0; m++) {
            Qr[t][l + m][l - m] = inv;    // q[l+m, l+|m|] = 1/sqrt2
            Qi[t][l + m][l + m] = -inv;   // q[l+m, l-|m|] = -i/sqrt2
        }
        Qr[t][l][l] = 1.0;
        for (int m = 1; m <= l; m++) {
            double sgn = (m & 1) ? -1.0 : 1.0;
            Qr[t][l + m][l + m] = sgn * inv;  // (-1)^m/sqrt2
            Qi[t][l + m][l - m] = sgn * inv;  // i(-1)^m/sqrt2
        }
        int ph = l & 3;  // multiply by (-i)^l
        for (int a = 0; a < 5; a++)
            for (int b = 0; b < 5; b++) {
                double r = Qr[t][a][b], im = Qi[t][a][b];
                if (ph == 1)      { Qr[t][a][b] =  im; Qi[t][a][b] = -r;  }
                else if (ph == 2) { Qr[t][a][b] = -r;  Qi[t][a][b] = -im; }
                else if (ph == 3) { Qr[t][a][b] = -im; Qi[t][a][b] =  r;  }
            }
    }

    // --- einsum 'ij,kl,nm,ikn->jlm' with conj(Q3); real part; Frobenius ---
    int n1 = 2 * l1 + 1, n2 = 2 * l2 + 1, n3 = 2 * l3 + 1;
    double Cr[5][5][5];
    double frob = 0.0;
    for (int j = 0; j < n1; j++)
        for (int l = 0; l < n2; l++)
            for (int m = 0; m < n3; m++) {
                double re = 0.0;
                for (int i = 0; i < n1; i++)
                    for (int k = 0; k < n2; k++)
                        for (int n = 0; n < n3; n++) {
                            double c = C[i][k][n];
                            if (c == 0.0) continue;
                            double ar = Qr[0][i][j], ai = Qi[0][i][j];
                            double br = Qr[1][k][l], bi = Qi[1][k][l];
                            double t1r = ar * br - ai * bi;
                            double t1i = ar * bi + ai * br;
                            double cr = Qr[2][n][m], ci = -Qi[2][n][m];  // conj
                            re += c * (t1r * cr - t1i * ci);
                        }
                Cr[j][l][m] = re;
                frob += re * re;
            }

    double alpha = (l3 == 0) ? (1.0 / 384.0) : (l3 == 1) ? (3.0 / 512.0) : (5.0 / 512.0);
    double scale = sqrt(alpha) / sqrt(frob);

    float* dst = g_W3 + p * 125;
    for (int j = 0; j < 5; j++)
        for (int l = 0; l < 5; l++)
            for (int m = 0; m < 5; m++)
                dst[j * 25 + l * 5 + m] =
                    (j < n1 && l < n2 && m < n3) ? (float)(Cr[j][l][m] * scale) : 0.0f;
}

// ---------------------------------------------------------------------------
// Packed f32x2 FMA (SASS FFMA2 — only reachable via PTX).
// ---------------------------------------------------------------------------
__device__ __forceinline__ void fma2(u64& d, u64 a, u64 b) {
    asm("fma.rn.f32x2 %0, %1, %2, %0;" : "+l"(d) : "l"(a), "l"(b));
}

__device__ __forceinline__ float2 u2f(u64 v) {
    float2 r;
    r.x = __uint_as_float((unsigned)(v & 0xffffffffULL));
    r.y = __uint_as_float((unsigned)(v >> 32));
    return r;
}

// acc slots: 0 = l0; 1..3 = l1 (k); 4..8 = l2 (k). [batch][slot][w-pair]
template <int S>
__device__ __forceinline__ void acc4(u64 (&acc)[2][9][2], u64 a0, u64 a1,
                                     const ulonglong2& wv) {
    fma2(acc[0][S][0], a0, wv.x);
    fma2(acc[0][S][1], a0, wv.y);
    fma2(acc[1][S][0], a1, wv.x);
    fma2(acc[1][S][1], a1, wv.y);
}

template <int P, int NK, int COFF, int OUT0>
__device__ __forceinline__ void do_path2(const ulonglong2* __restrict__ wsv,
                                         const float2* __restrict__ A0,
                                         const float2* __restrict__ A1,
                                         int u, int lane, u64 (&acc)[2][9][2]) {
    ulonglong2 wv = wsv[(size_t)(P * 128 + u) * 32 + lane];  // ws[p][u][w0..w0+3]
    if constexpr (NK == 1) {
        u64 a0 = *reinterpret_cast<const u64*>(A0 + COFF);
        u64 a1 = *reinterpret_cast<const u64*>(A1 + COFF);
        acc4<OUT0>(acc, a0, a1, wv);
    } else if constexpr (NK == 3) {
        ulonglong2 a0p = *reinterpret_cast<const ulonglong2*>(A0 + COFF);
        ulonglong2 a1p = *reinterpret_cast<const ulonglong2*>(A1 + COFF);
        u64 a0s = *reinterpret_cast<const u64*>(A0 + COFF + 2);
        u64 a1s = *reinterpret_cast<const u64*>(A1 + COFF + 2);
        acc4<OUT0 + 0>(acc, a0p.x, a1p.x, wv);
        acc4<OUT0 + 1>(acc, a0p.y, a1p.y, wv);
        acc4<OUT0 + 2>(acc, a0s, a1s, wv);
    } else {  // NK == 5
        ulonglong2 a0p = *reinterpret_cast<const ulonglong2*>(A0 + COFF);
        ulonglong2 a0q = *reinterpret_cast<const ulonglong2*>(A0 + COFF + 2);
        u64 a0s = *reinterpret_cast<const u64*>(A0 + COFF + 4);
        ulonglong2 a1p = *reinterpret_cast<const ulonglong2*>(A1 + COFF);
        ulonglong2 a1q = *reinterpret_cast<const ulonglong2*>(A1 + COFF + 2);
        u64 a1s = *reinterpret_cast<const u64*>(A1 + COFF + 4);
        acc4<OUT0 + 0>(acc, a0p.x, a1p.x, wv);
        acc4<OUT0 + 1>(acc, a0p.y, a1p.y, wv);
        acc4<OUT0 + 2>(acc, a0q.x, a1q.x, wv);
        acc4<OUT0 + 3>(acc, a0q.y, a1q.y, wv);
        acc4<OUT0 + 4>(acc, a0s, a1s, wv);
    }
}

// ---------------------------------------------------------------------------
// Main kernel. Dynamic smem: sG [TB][120] f32, then sA [TB*KC][ASTR] float2
// (A-values stored duplicated {a,a} so ld.shared.b64 feeds fma.rn.f32x2).
// Warp w_id handles batches 2*w_id, 2*w_id+1; lane owns w = 4*lane..4*lane+3.
// ---------------------------------------------------------------------------
__global__ void __launch_bounds__(NTHREADS)
tp_main(const float* __restrict__ x1, const float* __restrict__ x2,
        const float* __restrict__ ws, float* __restrict__ out) {
    extern __shared__ float smem[];
    float* sG = smem;                                          // TB*120 floats
    float2* sA = reinterpret_cast<float2*>(smem + TB * 120);   // TB*KC*ASTR float2

    const int tid = threadIdx.x;
    const int b0 = blockIdx.x * TB;
    const ulonglong2* wsv = reinterpret_cast<const ulonglong2*>(ws);

    // ---- G_p[i][k] = sum_j W3s[p][i][j][k] * x2[b][s2off[l2]+j] ----
    if (tid < TB * 11) {
        int b = tid / 11, p = tid % 11;
        int l1 = c_l1[p], l2 = c_l2[p], lo = c_lo[p], goff = c_goff[p];
        int nI = 2 * l1 + 1, nJ = 2 * l2 + 1, nK = 2 * lo + 1;
        const float* w3 = g_W3 + p * 125;
        const float* x2b = x2 + (size_t)(b0 + b) * 9 + c_s2off[l2];
        float* G = sG + b * 120 + goff;
        for (int i = 0; i < nI; i++)
            for (int k = 0; k < nK; k++) {
                float s = 0.0f;
                for (int j = 0; j < nJ; j++)
                    s = fmaf(w3[i * 25 + j * 5 + k], x2b[j], s);
                G[i * nK + k] = s;
            }
    }
    __syncthreads();

    const int w_id = tid >> 5;
    const int lane = tid & 31;
    const int bL0 = 2 * w_id;          // local batches this warp owns
    const int w0 = lane * 4;

    u64 acc[2][9][2];
#pragma unroll
    for (int bb = 0; bb < 2; bb++)
#pragma unroll
        for (int s = 0; s < 9; s++)
#pragma unroll
            for (int q = 0; q < 2; q++) acc[bb][s][q] = 0ULL;

    for (int uc = 0; uc < 128; uc += KC) {
        // ---- stage A[b][u][c] (duplicated), all 256 threads, one (b,u) each ----
        {
            int ab = tid >> 4, ul = tid & 15, u = uc + ul;
            float2* Arow = sA + (ab * KC + ul) * ASTR;
            const float* gb = sG + ab * 120;
            const float* x1b = x1 + (size_t)(b0 + ab) * 1152;
#pragma unroll
            for (int p = 0; p < 11; p++) {
                const int l1 = c_l1[p], lo = c_lo[p];
                const int nI = 2 * l1 + 1, nK = 2 * lo + 1;
                const float* xv = x1b + c_s1off[l1] + u * nI;
                const float* G = gb + c_goff[p];
                float2* Ap = Arow + c_aoff[p];
#pragma unroll 5
                for (int k = 0; k < nK; k++) {
                    float s = 0.0f;
                    for (int i = 0; i < nI; i++)
                        s = fmaf(xv[i], G[i * nK + k], s);
                    Ap[k] = make_float2(s, s);
                }
            }
        }
        __syncthreads();

        // ---- heavy contraction over this u-chunk (FFMA2-bound) ----
        const float2* aB0 = sA + (bL0 * KC) * ASTR;
        const float2* aB1 = sA + ((bL0 + 1) * KC) * ASTR;
#pragma unroll 4
        for (int ul = 0; ul < KC; ul++) {
            int u = uc + ul;
            const float2* A0 = aB0 + ul * ASTR;
            const float2* A1 = aB1 + ul * ASTR;
            do_path2<0, 1, 40, 0>(wsv, A0, A1, u, lane, acc);
            do_path2<1, 3, 24, 1>(wsv, A0, A1, u, lane, acc);
            do_path2<2, 5,  0, 4>(wsv, A0, A1, u, lane, acc);
            do_path2<3, 3, 28, 1>(wsv, A0, A1, u, lane, acc);
            do_path2<4, 1, 41, 0>(wsv, A0, A1, u, lane, acc);
            do_path2<5, 5,  6, 4>(wsv, A0, A1, u, lane, acc);
            do_path2<6, 3, 32, 1>(wsv, A0, A1, u, lane, acc);
            do_path2<7, 5, 12, 4>(wsv, A0, A1, u, lane, acc);
            do_path2<8, 3, 36, 1>(wsv, A0, A1, u, lane, acc);
            do_path2<9, 1, 42, 0>(wsv, A0, A1, u, lane, acc);
            do_path2<10,5, 18, 4>(wsv, A0, A1, u, lane, acc);
        }
        __syncthreads();   // sA about to be overwritten
    }

    // ---- write out: slot 0 -> l0; 1..3 -> l1; 4..8 -> l2 ----
#pragma unroll
    for (int bb = 0; bb < 2; bb++) {
        size_t base = (size_t)(b0 + bL0 + bb) * 1152;
#pragma unroll
        for (int q = 0; q < 2; q++) {
            int wA = w0 + 2 * q, wB = wA + 1;
            float2 v0 = u2f(acc[bb][0][q]);
            out[base + wA] = v0.x;
            out[base + wB] = v0.y;
#pragma unroll
            for (int k = 0; k < 3; k++) {
                float2 v = u2f(acc[bb][1 + k][q]);
                out[base + 128 + wA * 3 + k] = v.x;
                out[base + 128 + wB * 3 + k] = v.y;
            }
#pragma unroll
            for (int k = 0; k < 5; k++) {
                float2 v = u2f(acc[bb][4 + k][q]);
                out[base + 512 + wA * 5 + k] = v.x;
                out[base + 512 + wB * 5 + k] = v.y;
            }
        }
    }
}

// ---------------------------------------------------------------------------
extern "C" void kernel_launch(void* const* d_in, const int* in_sizes, int n_in,
                              void* d_out, int out_size) {
    const float* x1 = (const float*)d_in[0];
    const float* x2 = (const float*)d_in[1];
    const float* ws = (const float*)d_in[2];
    float* out = (float*)d_out;

    int B = in_sizes[0] / 1152;              // 32768
    int grid = B / TB;                       // 2048

    const int smem_bytes = TB * 120 * 4 + TB * KC * ASTR * 8;  // 7680 + 90112 = 97792
    cudaFuncSetAttribute(tp_main, cudaFuncAttributeMaxDynamicSharedMemorySize, smem_bytes);

    tp_init_w3<<<1, 32>>>();
    tp_main<<<grid, NTHREADS, smem_bytes>>>(x1, x2, ws, out);
}

// round 8
// speedup vs baseline: 1.1170x; 1.1170x over previous
#include <cuda_runtime.h>
#include <cuda_bf16.h>
#include <cstdint>

// ---------------------------------------------------------------------------
// FullyConnectedTensorProduct: 128x0e+128x1o+128x2e (x) 1x0e+1x1o+1x2e
//                              -> 128x0e+128x1o+128x2e, B = 32768
// Inputs: x1 [B,1152] f32, x2 [B,9] f32, ws [11,128,1,128] f32 -> out [B,1152]
//
// Factorization (MUL2 = 1):
//   G_p[i][k]   = sum_j C_p[i,j,k] * x2[b,j]               (tiny)
//   A_p[u][k]   = sum_i x1[b,u,i] * G_p[i][k]              (~2.5% of FLOPs)
//   out_p[w][k]+= sum_u ws[p][u][w] * A_p[u][k]            (dominant, FFMA2)
//
// R7 lesson: 36 u64 accumulators + unroll-4 LDG hoisting -> 255 regs, spills,
// 6.9 ms. This version: 2 w per thread (18 u64 acc = 36 regs), 2 batches per
// thread, __launch_bounds__(256,2) caps regs at 128, unroll 2.
//
// Path table p : (l1,l2,lo)
//  0:(0,0,0) 1:(0,1,1) 2:(0,2,2) 3:(1,0,1) 4:(1,1,0) 5:(1,1,2)
//  6:(1,2,1) 7:(2,0,2) 8:(2,1,1) 9:(2,2,0) 10:(2,2,2)
// ---------------------------------------------------------------------------

#define TB 8          // batches per block
#define KC 32         // u-chunk size
#define NTHREADS 256
#define ASTR 44       // sA row stride in float2 (352 B, 16B-aligned)

typedef unsigned long long u64;

// Runtime-indexed tables (init kernel + G stage) must be __constant__.
__constant__ int c_l1[11]   = {0,0,0,1,1,1,1,2,2,2,2};
__constant__ int c_l2[11]   = {0,1,2,0,1,1,2,0,1,2,2};
__constant__ int c_lo[11]   = {0,1,2,1,0,2,1,2,1,0,2};
__constant__ int c_goff[11] = {0,1,4,9,18,21,36,45,70,85,90};
__constant__ int c_s2off[3] = {0,1,4};

// Scaled Wigner-3j tensors: g_W3[p][i][j][k], padded 5x5x5, pre-multiplied by
// sqrt(alpha_p)/frobenius_norm.
__device__ float g_W3[11 * 125];

// ---------------------------------------------------------------------------
// Init kernel: real Wigner-3j exactly as the reference (fp64).
// ---------------------------------------------------------------------------
__device__ __forceinline__ double dfact(int n) {
    double r = 1.0;
    for (int i = 2; i <= n; i++) r *= (double)i;
    return r;
}

__global__ void tp_init_w3() {
    int p = threadIdx.x;
    if (p >= 11) return;
    const int l1 = c_l1[p], l2 = c_l2[p], l3 = c_lo[p];

    // --- SU(2) Clebsch-Gordan ---
    double C[5][5][5];
    for (int a = 0; a < 5; a++)
        for (int b = 0; b < 5; b++)
            for (int c = 0; c < 5; c++) C[a][b][c] = 0.0;

    for (int m1 = -l1; m1 <= l1; m1++) {
        for (int m2 = -l2; m2 <= l2; m2++) {
            int m3 = m1 + m2;
            if (m3 < -l3 || m3 > l3) continue;
            double pref = sqrt((double)(2 * l3 + 1) * dfact(l3 + l1 - l2) * dfact(l3 - l1 + l2) *
                               dfact(l1 + l2 - l3) / dfact(l1 + l2 + l3 + 1));
            pref *= sqrt(dfact(l3 + m3) * dfact(l3 - m3) * dfact(l1 - m1) * dfact(l1 + m1) *
                         dfact(l2 - m2) * dfact(l2 + m2));
            double s = 0.0;
            for (int k = 0; k <= l1 + l2 - l3; k++) {
                if (l1 - m1 - k < 0 || l2 + m2 - k < 0 ||
                    l3 - l2 + m1 + k < 0 || l3 - l1 - m2 + k < 0) continue;
                double term = 1.0 / (dfact(k) * dfact(l1 + l2 - l3 - k) * dfact(l1 - m1 - k) *
                                     dfact(l2 + m2 - k) * dfact(l3 - l2 + m1 + k) *
                                     dfact(l3 - l1 - m2 + k));
                s += (k & 1) ? -term : term;
            }
            C[l1 + m1][l2 + m2][l3 + m3] = pref * s;
        }
    }

    // --- real-basis matrices q(l) = (-i)^l * base (e3nn convention) ---
    double Qr[3][5][5], Qi[3][5][5];
    int ls[3] = {l1, l2, l3};
    for (int t = 0; t < 3; t++) {
        int l = ls[t];
        for (int a = 0; a < 5; a++)
            for (int b = 0; b < 5; b++) { Qr[t][a][b] = 0.0; Qi[t][a][b] = 0.0; }
        double inv = 1.0 / sqrt(2.0);
        for (int m = -l; m < 0; m++) {
            Qr[t][l + m][l - m] = inv;
            Qi[t][l + m][l + m] = -inv;
        }
        Qr[t][l][l] = 1.0;
        for (int m = 1; m <= l; m++) {
            double sgn = (m & 1) ? -1.0 : 1.0;
            Qr[t][l + m][l + m] = sgn * inv;
            Qi[t][l + m][l - m] = sgn * inv;
        }
        int ph = l & 3;  // multiply by (-i)^l
        for (int a = 0; a < 5; a++)
            for (int b = 0; b < 5; b++) {
                double r = Qr[t][a][b], im = Qi[t][a][b];
                if (ph == 1)      { Qr[t][a][b] =  im; Qi[t][a][b] = -r;  }
                else if (ph == 2) { Qr[t][a][b] = -r;  Qi[t][a][b] = -im; }
                else if (ph == 3) { Qr[t][a][b] = -im; Qi[t][a][b] =  r;  }
            }
    }

    // --- einsum 'ij,kl,nm,ikn->jlm' with conj(Q3); real part; Frobenius ---
    int n1 = 2 * l1 + 1, n2 = 2 * l2 + 1, n3 = 2 * l3 + 1;
    double Cr[5][5][5];
    double frob = 0.0;
    for (int j = 0; j < n1; j++)
        for (int l = 0; l < n2; l++)
            for (int m = 0; m < n3; m++) {
                double re = 0.0;
                for (int i = 0; i < n1; i++)
                    for (int k = 0; k < n2; k++)
                        for (int n = 0; n < n3; n++) {
                            double c = C[i][k][n];
                            if (c == 0.0) continue;
                            double ar = Qr[0][i][j], ai = Qi[0][i][j];
                            double br = Qr[1][k][l], bi = Qi[1][k][l];
                            double t1r = ar * br - ai * bi;
                            double t1i = ar * bi + ai * br;
                            double cr = Qr[2][n][m], ci = -Qi[2][n][m];  // conj
                            re += c * (t1r * cr - t1i * ci);
                        }
                Cr[j][l][m] = re;
                frob += re * re;
            }

    double alpha = (l3 == 0) ? (1.0 / 384.0) : (l3 == 1) ? (3.0 / 512.0) : (5.0 / 512.0);
    double scale = sqrt(alpha) / sqrt(frob);

    float* dst = g_W3 + p * 125;
    for (int j = 0; j < 5; j++)
        for (int l = 0; l < 5; l++)
            for (int m = 0; m < 5; m++)
                dst[j * 25 + l * 5 + m] =
                    (j < n1 && l < n2 && m < n3) ? (float)(Cr[j][l][m] * scale) : 0.0f;
}

// ---------------------------------------------------------------------------
// Packed f32x2 FMA (SASS FFMA2 — only reachable via PTX).
// ---------------------------------------------------------------------------
__device__ __forceinline__ void fma2(u64& d, u64 a, u64 b) {
    asm("fma.rn.f32x2 %0, %1, %2, %0;" : "+l"(d) : "l"(a), "l"(b));
}

__device__ __forceinline__ float2 u2f(u64 v) {
    float2 r;
    r.x = __uint_as_float((unsigned)(v & 0xffffffffULL));
    r.y = __uint_as_float((unsigned)(v >> 32));
    return r;
}

// ---------------------------------------------------------------------------
// A-staging: one path, compile-time geometry.
// ---------------------------------------------------------------------------
template <int L1V, int LOV, int S1, int GOFF, int AOFF>
__device__ __forceinline__ void stage_path(const float* __restrict__ x1b,
                                           const float* __restrict__ gb,
                                           float2* __restrict__ Arow, int u) {
    constexpr int nI = 2 * L1V + 1, nK = 2 * LOV + 1;
    float xv[nI];
#pragma unroll
    for (int i = 0; i < nI; i++) xv[i] = x1b[S1 + u * nI + i];
#pragma unroll
    for (int k = 0; k < nK; k++) {
        float s = 0.0f;
#pragma unroll
        for (int i = 0; i < nI; i++) s = fmaf(xv[i], gb[GOFF + i * nK + k], s);
        Arow[AOFF + k] = make_float2(s, s);   // duplicated {a,a} for f32x2
    }
}

// ---------------------------------------------------------------------------
// Hot-loop path: wv = ws[p][u][2wp..2wp+1] (u64), acc[batch][slot].
// Slots: 0 = l0; 1..3 = l1 k; 4..8 = l2 k.
// ---------------------------------------------------------------------------
template <int P, int NK, int COFF, int OUT0>
__device__ __forceinline__ void do_path(const u64* __restrict__ wrow,
                                        const float2* __restrict__ A0,
                                        const float2* __restrict__ A1,
                                        u64 (&acc)[2][9]) {
    u64 wv = wrow[P * 8192];    // + p*128*64 (base+immediate)
    if constexpr (NK == 1) {
        u64 a0 = *reinterpret_cast<const u64*>(A0 + COFF);
        u64 a1 = *reinterpret_cast<const u64*>(A1 + COFF);
        fma2(acc[0][OUT0], a0, wv);
        fma2(acc[1][OUT0], a1, wv);
    } else if constexpr (NK == 3) {
        ulonglong2 a0p = *reinterpret_cast<const ulonglong2*>(A0 + COFF);
        u64 a0s = *reinterpret_cast<const u64*>(A0 + COFF + 2);
        ulonglong2 a1p = *reinterpret_cast<const ulonglong2*>(A1 + COFF);
        u64 a1s = *reinterpret_cast<const u64*>(A1 + COFF + 2);
        fma2(acc[0][OUT0 + 0], a0p.x, wv);
        fma2(acc[0][OUT0 + 1], a0p.y, wv);
        fma2(acc[0][OUT0 + 2], a0s, wv);
        fma2(acc[1][OUT0 + 0], a1p.x, wv);
        fma2(acc[1][OUT0 + 1], a1p.y, wv);
        fma2(acc[1][OUT0 + 2], a1s, wv);
    } else {  // NK == 5
        ulonglong2 a0p = *reinterpret_cast<const ulonglong2*>(A0 + COFF);
        ulonglong2 a0q = *reinterpret_cast<const ulonglong2*>(A0 + COFF + 2);
        u64 a0s = *reinterpret_cast<const u64*>(A0 + COFF + 4);
        ulonglong2 a1p = *reinterpret_cast<const ulonglong2*>(A1 + COFF);
        ulonglong2 a1q = *reinterpret_cast<const ulonglong2*>(A1 + COFF + 2);
        u64 a1s = *reinterpret_cast<const u64*>(A1 + COFF + 4);
        fma2(acc[0][OUT0 + 0], a0p.x, wv);
        fma2(acc[0][OUT0 + 1], a0p.y, wv);
        fma2(acc[0][OUT0 + 2], a0q.x, wv);
        fma2(acc[0][OUT0 + 3], a0q.y, wv);
        fma2(acc[0][OUT0 + 4], a0s, wv);
        fma2(acc[1][OUT0 + 0], a1p.x, wv);
        fma2(acc[1][OUT0 + 1], a1p.y, wv);
        fma2(acc[1][OUT0 + 2], a1q.x, wv);
        fma2(acc[1][OUT0 + 3], a1q.y, wv);
        fma2(acc[1][OUT0 + 4], a1s, wv);
    }
}

// ---------------------------------------------------------------------------
// Main kernel. Thread t: batch-pair bp = t>>6 (2 batches), w-pair wp = t&63
// (w = 2wp, 2wp+1). acc[2][9] u64 = 36 regs. 2 CTAs/SM (regs capped 128,
// smem 2x94KB = 188KB <= 228KB).
// ---------------------------------------------------------------------------
__global__ void __launch_bounds__(NTHREADS, 2)
tp_main(const float* __restrict__ x1, const float* __restrict__ x2,
        const float* __restrict__ ws, float* __restrict__ out) {
    extern __shared__ float smem[];
    float* sG = smem;                                          // TB*120 floats
    float2* sA = reinterpret_cast<float2*>(smem + TB * 120);   // TB*KC*ASTR float2

    const int tid = threadIdx.x;
    const int b0 = blockIdx.x * TB;

    // ---- G_p[i][k] = sum_j W3s[p][i][j][k] * x2[b][s2off[l2]+j] ----
    if (tid < TB * 11) {
        int b = tid / 11, p = tid % 11;
        int l1 = c_l1[p], l2 = c_l2[p], lo = c_lo[p], goff = c_goff[p];
        int nI = 2 * l1 + 1, nJ = 2 * l2 + 1, nK = 2 * lo + 1;
        const float* w3 = g_W3 + p * 125;
        const float* x2b = x2 + (size_t)(b0 + b) * 9 + c_s2off[l2];
        float* G = sG + b * 120 + goff;
        for (int i = 0; i < nI; i++)
            for (int k = 0; k < nK; k++) {
                float s = 0.0f;
                for (int j = 0; j < nJ; j++)
                    s = fmaf(w3[i * 25 + j * 5 + k], x2b[j], s);
                G[i * nK + k] = s;
            }
    }
    __syncthreads();

    const int bp = tid >> 6;        // batch-pair 0..3
    const int wp = tid & 63;        // w-pair; w = 2wp, 2wp+1
    const u64* wsv = reinterpret_cast<const u64*>(ws);

    u64 acc[2][9];
#pragma unroll
    for (int bb = 0; bb < 2; bb++)
#pragma unroll
        for (int s = 0; s < 9; s++) acc[bb][s] = 0ULL;

    const int ab = tid >> 5;        // staging: local batch 0..7
    const int ul = tid & 31;        // staging: u within chunk
    const float* x1b = x1 + (size_t)(b0 + ab) * 1152;
    const float* gb = sG + ab * 120;

    for (int uc = 0; uc < 128; uc += KC) {
        // ---- stage A[b][u][c] (duplicated {a,a}); 256 threads, one (b,u) each
        {
            int u = uc + ul;
            float2* Arow = sA + (ab * KC + ul) * ASTR;
            // p: <l1, lo, s1off, goff, aoff>
            stage_path<0, 0,   0,  0, 40>(x1b, gb, Arow, u);   // p0
            stage_path<0, 1,   0,  1, 24>(x1b, gb, Arow, u);   // p1
            stage_path<0, 2,   0,  4,  0>(x1b, gb, Arow, u);   // p2
            stage_path<1, 1, 128,  9, 28>(x1b, gb, Arow, u);   // p3
            stage_path<1, 0, 128, 18, 41>(x1b, gb, Arow, u);   // p4
            stage_path<1, 2, 128, 21,  6>(x1b, gb, Arow, u);   // p5
            stage_path<1, 1, 128, 36, 32>(x1b, gb, Arow, u);   // p6
            stage_path<2, 2, 512, 45, 12>(x1b, gb, Arow, u);   // p7
            stage_path<2, 1, 512, 70, 36>(x1b, gb, Arow, u);   // p8
            stage_path<2, 0, 512, 85, 42>(x1b, gb, Arow, u);   // p9
            stage_path<2, 2, 512, 90, 18>(x1b, gb, Arow, u);   // p10
        }
        __syncthreads();

        // ---- heavy contraction over this u-chunk (FFMA2-bound) ----
        const float2* aB0 = sA + ((2 * bp) * KC) * ASTR;
        const float2* aB1 = sA + ((2 * bp + 1) * KC) * ASTR;
#pragma unroll 2
        for (int uli = 0; uli < KC; uli++) {
            const u64* wrow = wsv + (size_t)(uc + uli) * 64 + wp;
            const float2* A0 = aB0 + uli * ASTR;
            const float2* A1 = aB1 + uli * ASTR;
            do_path<0, 1, 40, 0>(wrow, A0, A1, acc);
            do_path<1, 3, 24, 1>(wrow, A0, A1, acc);
            do_path<2, 5,  0, 4>(wrow, A0, A1, acc);
            do_path<3, 3, 28, 1>(wrow, A0, A1, acc);
            do_path<4, 1, 41, 0>(wrow, A0, A1, acc);
            do_path<5, 5,  6, 4>(wrow, A0, A1, acc);
            do_path<6, 3, 32, 1>(wrow, A0, A1, acc);
            do_path<7, 5, 12, 4>(wrow, A0, A1, acc);
            do_path<8, 3, 36, 1>(wrow, A0, A1, acc);
            do_path<9, 1, 42, 0>(wrow, A0, A1, acc);
            do_path<10,5, 18, 4>(wrow, A0, A1, acc);
        }
        __syncthreads();   // sA about to be overwritten
    }

    // ---- write out: slot 0 -> l0; 1..3 -> l1; 4..8 -> l2 ----
#pragma unroll
    for (int bb = 0; bb < 2; bb++) {
        size_t base = (size_t)(b0 + 2 * bp + bb) * 1152;
        int wA = 2 * wp, wB = 2 * wp + 1;
        float2 v0 = u2f(acc[bb][0]);
        out[base + wA] = v0.x;
        out[base + wB] = v0.y;
#pragma unroll
        for (int k = 0; k < 3; k++) {
            float2 v = u2f(acc[bb][1 + k]);
            out[base + 128 + wA * 3 + k] = v.x;
            out[base + 128 + wB * 3 + k] = v.y;
        }
#pragma unroll
        for (int k = 0; k < 5; k++) {
            float2 v = u2f(acc[bb][4 + k]);
            out[base + 512 + wA * 5 + k] = v.x;
            out[base + 512 + wB * 5 + k] = v.y;
        }
    }
}

// ---------------------------------------------------------------------------
extern "C" void kernel_launch(void* const* d_in, const int* in_sizes, int n_in,
                              void* d_out, int out_size) {
    const float* x1 = (const float*)d_in[0];
    const float* x2 = (const float*)d_in[1];
    const float* ws = (const float*)d_in[2];
    float* out = (float*)d_out;

    int B = in_sizes[0] / 1152;              // 32768
    int grid = B / TB;                       // 4096

    const int smem_bytes = TB * 120 * 4 + TB * KC * ASTR * 8;  // 3840 + 90112 = 93952
    cudaFuncSetAttribute(tp_main, cudaFuncAttributeMaxDynamicSharedMemorySize, smem_bytes);

    tp_init_w3<<<1, 32>>>();
    tp_main<<<grid, NTHREADS, smem_bytes>>>(x1, x2, ws, out);
}

// round 11
// speedup vs baseline: 1.2238x; 1.0956x over previous
#include <cuda_runtime.h>
#include <cuda_bf16.h>
#include <cstdint>

// ---------------------------------------------------------------------------
// FullyConnectedTensorProduct: 128x0e+128x1o+128x2e (x) 1x0e+1x1o+1x2e
//                              -> 128x0e+128x1o+128x2e, B = 32768
// Inputs: x1 [B,1152] f32, x2 [B,9] f32, ws [11,128,1,128] f32 -> out [B,1152]
//
// R8 lesson: w-axis f32x2 packing forces duplicated A in smem -> 68 L1
// wavefronts vs 35 FMA cyc per warp-u -> L1-bound (fma=31.6%, L1=88.6%).
// R9/R11: batch-axis f32x2 packing. A stored interleaved (b_even,b_odd) float2,
// contiguous c=0..34 row; ws lane-duplicated via 2 ALU movs (ALU has slack).
// Thread: 2 w x 2 batch-pairs (4 batches), acc[2][2][9] u64 = 72 regs.
// Per warp-u: FMA 70 SM-cyc vs L1 ~66 wavefronts -> FMA-bound.
// (R10 run was lost to an infra fault: "device busy/unavailable" at init.)
//
// A-row path order (c index): p2:0-4, p5:5-9, p7:10-14, p10:15-19,
//   p1:20-22, p3:23-25, p6:26-28, p8:29-31, p0:32, p4:33, p9:34
// Output slots: 0 = l0; 1..3 = l1 k; 4..8 = l2 k.
// ---------------------------------------------------------------------------

#define TB 16         // batches per block (8 pairs)
#define KC 16         // u-chunk size
#define NTHREADS 256
#define ASTR 36       // sA row stride in float2 (288 B, 16B-aligned; 18 ull2)

typedef unsigned long long u64;

// Runtime-indexed tables (init kernel + G stage) must be __constant__.
__constant__ int c_l1[11]   = {0,0,0,1,1,1,1,2,2,2,2};
__constant__ int c_l2[11]   = {0,1,2,0,1,1,2,0,1,2,2};
__constant__ int c_lo[11]   = {0,1,2,1,0,2,1,2,1,0,2};
__constant__ int c_goff[11] = {0,1,4,9,18,21,36,45,70,85,90};
__constant__ int c_s2off[3] = {0,1,4};

// Scaled Wigner-3j tensors: g_W3[p][i][j][k], padded 5x5x5, pre-multiplied by
// sqrt(alpha_p)/frobenius_norm.
__device__ float g_W3[11 * 125];

// ---------------------------------------------------------------------------
// Init kernel: real Wigner-3j exactly as the reference (fp64).
// ---------------------------------------------------------------------------
__device__ __forceinline__ double dfact(int n) {
    double r = 1.0;
    for (int i = 2; i <= n; i++) r *= (double)i;
    return r;
}

__global__ void tp_init_w3() {
    int p = threadIdx.x;
    if (p >= 11) return;
    const int l1 = c_l1[p], l2 = c_l2[p], l3 = c_lo[p];

    // --- SU(2) Clebsch-Gordan ---
    double C[5][5][5];
    for (int a = 0; a < 5; a++)
        for (int b = 0; b < 5; b++)
            for (int c = 0; c < 5; c++) C[a][b][c] = 0.0;

    for (int m1 = -l1; m1 <= l1; m1++) {
        for (int m2 = -l2; m2 <= l2; m2++) {
            int m3 = m1 + m2;
            if (m3 < -l3 || m3 > l3) continue;
            double pref = sqrt((double)(2 * l3 + 1) * dfact(l3 + l1 - l2) * dfact(l3 - l1 + l2) *
                               dfact(l1 + l2 - l3) / dfact(l1 + l2 + l3 + 1));
            pref *= sqrt(dfact(l3 + m3) * dfact(l3 - m3) * dfact(l1 - m1) * dfact(l1 + m1) *
                         dfact(l2 - m2) * dfact(l2 + m2));
            double s = 0.0;
            for (int k = 0; k <= l1 + l2 - l3; k++) {
                if (l1 - m1 - k < 0 || l2 + m2 - k < 0 ||
                    l3 - l2 + m1 + k < 0 || l3 - l1 - m2 + k < 0) continue;
                double term = 1.0 / (dfact(k) * dfact(l1 + l2 - l3 - k) * dfact(l1 - m1 - k) *
                                     dfact(l2 + m2 - k) * dfact(l3 - l2 + m1 + k) *
                                     dfact(l3 - l1 - m2 + k));
                s += (k & 1) ? -term : term;
            }
            C[l1 + m1][l2 + m2][l3 + m3] = pref * s;
        }
    }

    // --- real-basis matrices q(l) = (-i)^l * base (e3nn convention) ---
    double Qr[3][5][5], Qi[3][5][5];
    int ls[3] = {l1, l2, l3};
    for (int t = 0; t < 3; t++) {
        int l = ls[t];
        for (int a = 0; a < 5; a++)
            for (int b = 0; b < 5; b++) { Qr[t][a][b] = 0.0; Qi[t][a][b] = 0.0; }
        double inv = 1.0 / sqrt(2.0);
        for (int m = -l; m < 0; m++) {
            Qr[t][l + m][l - m] = inv;
            Qi[t][l + m][l + m] = -inv;
        }
        Qr[t][l][l] = 1.0;
        for (int m = 1; m <= l; m++) {
            double sgn = (m & 1) ? -1.0 : 1.0;
            Qr[t][l + m][l + m] = sgn * inv;
            Qi[t][l + m][l - m] = sgn * inv;
        }
        int ph = l & 3;  // multiply by (-i)^l
        for (int a = 0; a < 5; a++)
            for (int b = 0; b < 5; b++) {
                double r = Qr[t][a][b], im = Qi[t][a][b];
                if (ph == 1)      { Qr[t][a][b] =  im; Qi[t][a][b] = -r;  }
                else if (ph == 2) { Qr[t][a][b] = -r;  Qi[t][a][b] = -im; }
                else if (ph == 3) { Qr[t][a][b] = -im; Qi[t][a][b] =  r;  }
            }
    }

    // --- einsum 'ij,kl,nm,ikn->jlm' with conj(Q3); real part; Frobenius ---
    int n1 = 2 * l1 + 1, n2 = 2 * l2 + 1, n3 = 2 * l3 + 1;
    double Cr[5][5][5];
    double frob = 0.0;
    for (int j = 0; j < n1; j++)
        for (int l = 0; l < n2; l++)
            for (int m = 0; m < n3; m++) {
                double re = 0.0;
                for (int i = 0; i < n1; i++)
                    for (int k = 0; k < n2; k++)
                        for (int n = 0; n < n3; n++) {
                            double c = C[i][k][n];
                            if (c == 0.0) continue;
                            double ar = Qr[0][i][j], ai = Qi[0][i][j];
                            double br = Qr[1][k][l], bi = Qi[1][k][l];
                            double t1r = ar * br - ai * bi;
                            double t1i = ar * bi + ai * br;
                            double cr = Qr[2][n][m], ci = -Qi[2][n][m];  // conj
                            re += c * (t1r * cr - t1i * ci);
                        }
                Cr[j][l][m] = re;
                frob += re * re;
            }

    double alpha = (l3 == 0) ? (1.0 / 384.0) : (l3 == 1) ? (3.0 / 512.0) : (5.0 / 512.0);
    double scale = sqrt(alpha) / sqrt(frob);

    float* dst = g_W3 + p * 125;
    for (int j = 0; j < 5; j++)
        for (int l = 0; l < 5; l++)
            for (int m = 0; m < 5; m++)
                dst[j * 25 + l * 5 + m] =
                    (j < n1 && l < n2 && m < n3) ? (float)(Cr[j][l][m] * scale) : 0.0f;
}

// ---------------------------------------------------------------------------
// Packed f32x2 FMA (SASS FFMA2 — only reachable via PTX).
// ---------------------------------------------------------------------------
__device__ __forceinline__ void fma2(u64& d, u64 a, u64 b) {
    asm("fma.rn.f32x2 %0, %1, %2, %0;" : "+l"(d) : "l"(a), "l"(b));
}

__device__ __forceinline__ float2 u2f(u64 v) {
    float2 r;
    r.x = __uint_as_float((unsigned)(v & 0xffffffffULL));
    r.y = __uint_as_float((unsigned)(v >> 32));
    return r;
}

// Split a (w, w+1) u64 into two lane-duplicated u64s: {w,w} and {w+1,w+1}.
__device__ __forceinline__ void dups(u64 v, u64& lo2, u64& hi2) {
    unsigned lo, hi;
    asm("mov.b64 {%0,%1}, %2;" : "=r"(lo), "=r"(hi) : "l"(v));
    asm("mov.b64 %0, {%1,%1};" : "=l"(lo2) : "r"(lo));
    asm("mov.b64 %0, {%1,%1};" : "=l"(hi2) : "r"(hi));
}

// ---------------------------------------------------------------------------
// Staging: one path, compile-time geometry; writes one f32 lane of the
// interleaved (b_even, b_odd) float2 A-row.
// ---------------------------------------------------------------------------
template <int L1V, int LOV, int S1, int GOFF, int AOFF>
__device__ __forceinline__ void stage_path(const float* __restrict__ x1b,
                                           const float* __restrict__ gb,
                                           float* __restrict__ ArowF,  // float* into float2 row
                                           int lane, int u) {
    constexpr int nI = 2 * L1V + 1, nK = 2 * LOV + 1;
    float xv[nI];
#pragma unroll
    for (int i = 0; i < nI; i++) xv[i] = x1b[S1 + u * nI + i];
#pragma unroll
    for (int k = 0; k < nK; k++) {
        float s = 0.0f;
#pragma unroll
        for (int i = 0; i < nI; i++) s = fmaf(xv[i], gb[GOFF + i * nK + k], s);
        ArowF[(AOFF + k) * 2 + lane] = s;
    }
}

// ---------------------------------------------------------------------------
// Hot-loop regions. acc[wi][pair][slot]; wrow = &ws_u64[u*64 + wp].
// ---------------------------------------------------------------------------

// Two NK=5 paths (10 consecutive c at ull2 offset C2), both into slots S0..S0+4.
template <int PA, int PB, int C2, int S0>
__device__ __forceinline__ void region10(const u64* __restrict__ wrow,
                                         const ulonglong2* __restrict__ A0r,
                                         const ulonglong2* __restrict__ A1r,
                                         u64 (&acc)[2][2][9]) {
    u64 wa = wrow[PA * 8192], wb = wrow[PB * 8192];
    u64 wa0, wa1, wb0, wb1;
    dups(wa, wa0, wa1);
    dups(wb, wb0, wb1);
#pragma unroll
    for (int pr = 0; pr < 2; pr++) {
        const ulonglong2* Ar = pr ? A1r : A0r;
        ulonglong2 x0 = Ar[C2], x1 = Ar[C2 + 1], x2 = Ar[C2 + 2],
                   x3 = Ar[C2 + 3], x4 = Ar[C2 + 4];
        fma2(acc[0][pr][S0 + 0], x0.x, wa0); fma2(acc[1][pr][S0 + 0], x0.x, wa1);
        fma2(acc[0][pr][S0 + 1], x0.y, wa0); fma2(acc[1][pr][S0 + 1], x0.y, wa1);
        fma2(acc[0][pr][S0 + 2], x1.x, wa0); fma2(acc[1][pr][S0 + 2], x1.x, wa1);
        fma2(acc[0][pr][S0 + 3], x1.y, wa0); fma2(acc[1][pr][S0 + 3], x1.y, wa1);
        fma2(acc[0][pr][S0 + 4], x2.x, wa0); fma2(acc[1][pr][S0 + 4], x2.x, wa1);
        fma2(acc[0][pr][S0 + 0], x2.y, wb0); fma2(acc[1][pr][S0 + 0], x2.y, wb1);
        fma2(acc[0][pr][S0 + 1], x3.x, wb0); fma2(acc[1][pr][S0 + 1], x3.x, wb1);
        fma2(acc[0][pr][S0 + 2], x3.y, wb0); fma2(acc[1][pr][S0 + 2], x3.y, wb1);
        fma2(acc[0][pr][S0 + 3], x4.x, wb0); fma2(acc[1][pr][S0 + 3], x4.x, wb1);
        fma2(acc[0][pr][S0 + 4], x4.y, wb0); fma2(acc[1][pr][S0 + 4], x4.y, wb1);
    }
}

// Two NK=3 paths (6 consecutive c at ull2 offset C2), both into slots S0..S0+2.
template <int PA, int PB, int C2, int S0>
__device__ __forceinline__ void region6(const u64* __restrict__ wrow,
                                        const ulonglong2* __restrict__ A0r,
                                        const ulonglong2* __restrict__ A1r,
                                        u64 (&acc)[2][2][9]) {
    u64 wa = wrow[PA * 8192], wb = wrow[PB * 8192];
    u64 wa0, wa1, wb0, wb1;
    dups(wa, wa0, wa1);
    dups(wb, wb0, wb1);
#pragma unroll
    for (int pr = 0; pr < 2; pr++) {
        const ulonglong2* Ar = pr ? A1r : A0r;
        ulonglong2 x0 = Ar[C2], x1 = Ar[C2 + 1], x2 = Ar[C2 + 2];
        fma2(acc[0][pr][S0 + 0], x0.x, wa0); fma2(acc[1][pr][S0 + 0], x0.x, wa1);
        fma2(acc[0][pr][S0 + 1], x0.y, wa0); fma2(acc[1][pr][S0 + 1], x0.y, wa1);
        fma2(acc[0][pr][S0 + 2], x1.x, wa0); fma2(acc[1][pr][S0 + 2], x1.x, wa1);
        fma2(acc[0][pr][S0 + 0], x1.y, wb0); fma2(acc[1][pr][S0 + 0], x1.y, wb1);
        fma2(acc[0][pr][S0 + 1], x2.x, wb0); fma2(acc[1][pr][S0 + 1], x2.x, wb1);
        fma2(acc[0][pr][S0 + 2], x2.y, wb0); fma2(acc[1][pr][S0 + 2], x2.y, wb1);
    }
}

// Three NK=1 paths (c at ull2 offset C2: x.x=PA, x.y=PB; u64 at float2 idx CF=PC),
// all into slot S0.
template <int PA, int PB, int PC, int C2, int CF, int S0>
__device__ __forceinline__ void region3(const u64* __restrict__ wrow,
                                        const ulonglong2* __restrict__ A0r,
                                        const ulonglong2* __restrict__ A1r,
                                        u64 (&acc)[2][2][9]) {
    u64 wa = wrow[PA * 8192], wb = wrow[PB * 8192], wc = wrow[PC * 8192];
    u64 wa0, wa1, wb0, wb1, wc0, wc1;
    dups(wa, wa0, wa1);
    dups(wb, wb0, wb1);
    dups(wc, wc0, wc1);
#pragma unroll
    for (int pr = 0; pr < 2; pr++) {
        const ulonglong2* Ar = pr ? A1r : A0r;
        ulonglong2 x0 = Ar[C2];
        u64 x2 = reinterpret_cast<const u64*>(Ar)[CF];
        fma2(acc[0][pr][S0], x0.x, wa0); fma2(acc[1][pr][S0], x0.x, wa1);
        fma2(acc[0][pr][S0], x0.y, wb0); fma2(acc[1][pr][S0], x0.y, wb1);
        fma2(acc[0][pr][S0], x2,   wc0); fma2(acc[1][pr][S0], x2,   wc1);
    }
}

// ---------------------------------------------------------------------------
// Main kernel. Block: 16 batches (8 pairs), 8 warps.
//   warp = wg*2 + wh: wg = pair-group (owns pairs 2wg, 2wg+1 = batches 4wg..4wg+3)
//                     wh = w-half; thread w-pair wp = wh*32 + lane; w = 2wp+wi.
// acc[2 wi][2 pair][9 slot] u64 = 72 regs. 2 CTAs/SM (regs <= 128, smem 44.5KB).
// ---------------------------------------------------------------------------
__global__ void __launch_bounds__(NTHREADS, 2)
tp_main(const float* __restrict__ x1, const float* __restrict__ x2,
        const float* __restrict__ ws, float* __restrict__ out) {
    extern __shared__ float smem[];
    float* sG = smem;                                          // TB*120 floats
    float2* sA = reinterpret_cast<float2*>(smem + TB * 120);   // 8 pairs * KC * ASTR

    const int tid = threadIdx.x;
    const int b0 = blockIdx.x * TB;

    // ---- G_p[i][k] = sum_j W3s[p][i][j][k] * x2[b][s2off[l2]+j] ----
    if (tid < TB * 11) {
        int b = tid / 11, p = tid % 11;
        int l1 = c_l1[p], l2 = c_l2[p], lo = c_lo[p], goff = c_goff[p];
        int nI = 2 * l1 + 1, nJ = 2 * l2 + 1, nK = 2 * lo + 1;
        const float* w3 = g_W3 + p * 125;
        const float* x2b = x2 + (size_t)(b0 + b) * 9 + c_s2off[l2];
        float* G = sG + b * 120 + goff;
        for (int i = 0; i < nI; i++)
            for (int k = 0; k < nK; k++) {
                float s = 0.0f;
                for (int j = 0; j < nJ; j++)
                    s = fmaf(w3[i * 25 + j * 5 + k], x2b[j], s);
                G[i * nK + k] = s;
            }
    }
    __syncthreads();

    const int warp = tid >> 5;
    const int lane = tid & 31;
    const int wg = warp >> 1;          // pair-group 0..3
    const int wh = warp & 1;           // w-half
    const int wp = wh * 32 + lane;     // w-pair 0..63; w = 2wp, 2wp+1
    const u64* wsv = reinterpret_cast<const u64*>(ws);

    u64 acc[2][2][9];
#pragma unroll
    for (int wi = 0; wi < 2; wi++)
#pragma unroll
        for (int pr = 0; pr < 2; pr++)
#pragma unroll
            for (int s = 0; s < 9; s++) acc[wi][pr][s] = 0ULL;

    // staging job: (b, ul) = (tid>>4, tid&15); writes lane b&1 of pair b>>1
    const int sb = tid >> 4;
    const int sul = tid & 15;
    const int sln = sb & 1;
    const float* x1b = x1 + (size_t)(b0 + sb) * 1152;
    const float* gb = sG + sb * 120;
    float* ArowF = reinterpret_cast<float*>(sA + ((sb >> 1) * KC + sul) * ASTR);

    const int pA = 2 * wg, pB = 2 * wg + 1;   // consumption pair rows

    for (int uc = 0; uc < 128; uc += KC) {
        // ---- stage A[pair][u][c] interleaved (b_even, b_odd) ----
        {
            int u = uc + sul;
            // p: <l1, lo, s1off, goff, aoff(c-index)>
            stage_path<0, 2,   0,  4,  0>(x1b, gb, ArowF, sln, u);   // p2
            stage_path<1, 2, 128, 21,  5>(x1b, gb, ArowF, sln, u);   // p5
            stage_path<2, 2, 512, 45, 10>(x1b, gb, ArowF, sln, u);   // p7
            stage_path<2, 2, 512, 90, 15>(x1b, gb, ArowF, sln, u);   // p10
            stage_path<0, 1,   0,  1, 20>(x1b, gb, ArowF, sln, u);   // p1
            stage_path<1, 1, 128,  9, 23>(x1b, gb, ArowF, sln, u);   // p3
            stage_path<1, 1, 128, 36, 26>(x1b, gb, ArowF, sln, u);   // p6
            stage_path<2, 1, 512, 70, 29>(x1b, gb, ArowF, sln, u);   // p8
            stage_path<0, 0,   0,  0, 32>(x1b, gb, ArowF, sln, u);   // p0
            stage_path<1, 0, 128, 18, 33>(x1b, gb, ArowF, sln, u);   // p4
            stage_path<2, 0, 512, 85, 34>(x1b, gb, ArowF, sln, u);   // p9
        }
        __syncthreads();

        // ---- heavy contraction over this u-chunk (FFMA2-bound) ----
#pragma unroll 1
        for (int ul = 0; ul < KC; ul++) {
            const u64* wrow = wsv + (size_t)(uc + ul) * 64 + wp;
            const ulonglong2* A0r =
                reinterpret_cast<const ulonglong2*>(sA + (pA * KC + ul) * ASTR);
            const ulonglong2* A1r =
                reinterpret_cast<const ulonglong2*>(sA + (pB * KC + ul) * ASTR);
            region10<2, 5,  0, 4>(wrow, A0r, A1r, acc);   // p2,p5  -> l2 slots
            region10<7, 10, 5, 4>(wrow, A0r, A1r, acc);   // p7,p10 -> l2 slots
            region6 <1, 3, 10, 1>(wrow, A0r, A1r, acc);   // p1,p3  -> l1 slots
            region6 <6, 8, 13, 1>(wrow, A0r, A1r, acc);   // p6,p8  -> l1 slots
            region3 <0, 4, 9, 16, 34, 0>(wrow, A0r, A1r, acc);  // p0,p4,p9 -> l0
        }
        __syncthreads();   // sA about to be overwritten
    }

    // ---- write out: lanes = (b_even, b_odd) of pair; slots -> segments ----
#pragma unroll
    for (int pr = 0; pr < 2; pr++) {
#pragma unroll
        for (int wi = 0; wi < 2; wi++) {
            int w = 2 * wp + wi;
#pragma unroll
            for (int s = 0; s < 9; s++) {
                float2 v = u2f(acc[wi][pr][s]);
                size_t baseE = (size_t)(b0 + 4 * wg + 2 * pr) * 1152;
                size_t baseO = baseE + 1152;
                int off;
                if (s == 0)      off = w;
                else if (s < 4)  off = 128 + w * 3 + (s - 1);
                else             off = 512 + w * 5 + (s - 4);
                out[baseE + off] = v.x;
                out[baseO + off] = v.y;
            }
        }
    }
}

// ---------------------------------------------------------------------------
extern "C" void kernel_launch(void* const* d_in, const int* in_sizes, int n_in,
                              void* d_out, int out_size) {
    const float* x1 = (const float*)d_in[0];
    const float* x2 = (const float*)d_in[1];
    const float* ws = (const float*)d_in[2];
    float* out = (float*)d_out;

    int B = in_sizes[0] / 1152;              // 32768
    int grid = B / TB;                       // 2048

    const int smem_bytes = TB * 120 * 4 + (TB / 2) * KC * ASTR * 8;  // 7680+36864=44544
    cudaFuncSetAttribute(tp_main, cudaFuncAttributeMaxDynamicSharedMemorySize, smem_bytes);

    tp_init_w3<<<1, 32>>>();
    tp_main<<<grid, NTHREADS, smem_bytes>>>(x1, x2, ws, out);
}

// round 12
// speedup vs baseline: 6.7910x; 5.5490x over previous
#include <cuda_runtime.h>
#include <cuda_bf16.h>
#include <cstdint>

// ---------------------------------------------------------------------------
// FullyConnectedTensorProduct: 128x0e+128x1o+128x2e (x) 1x0e+1x1o+1x2e
//                              -> 128x0e+128x1o+128x2e, B = 32768
// Inputs: x1 [B,1152] f32, x2 [B,9] f32, ws [11,128,1,128] f32 -> out [B,1152]
//
// R11 post-mortem: a constant ~4.66 ms per launch was tp_init_w3 (1 block,
// 11 threads, serial fp64 einsum). R12: init parallelized (11 blocks x 128
// threads, per-entry work) -> ~15 us. tp_main is unchanged from R11
// (1.013 ms, fma=48.6%, L1=73.1%).
//
// A-row path order (c index): p2:0-4, p5:5-9, p7:10-14, p10:15-19,
//   p1:20-22, p3:23-25, p6:26-28, p8:29-31, p0:32, p4:33, p9:34
// Output slots: 0 = l0; 1..3 = l1 k; 4..8 = l2 k.
// ---------------------------------------------------------------------------

#define TB 16         // batches per block (8 pairs)
#define KC 16         // u-chunk size
#define NTHREADS 256
#define ASTR 36       // sA row stride in float2 (288 B, 16B-aligned; 18 ull2)

typedef unsigned long long u64;

// Runtime-indexed tables must be __constant__.
__constant__ int c_l1[11]   = {0,0,0,1,1,1,1,2,2,2,2};
__constant__ int c_l2[11]   = {0,1,2,0,1,1,2,0,1,2,2};
__constant__ int c_lo[11]   = {0,1,2,1,0,2,1,2,1,0,2};
__constant__ int c_goff[11] = {0,1,4,9,18,21,36,45,70,85,90};
__constant__ int c_s2off[3] = {0,1,4};

// Scaled Wigner-3j tensors: g_W3[p][i][j][k], padded 5x5x5, pre-multiplied by
// sqrt(alpha_p)/frobenius_norm.
__device__ float g_W3[11 * 125];

// ---------------------------------------------------------------------------
// Init kernel v2 (parallel): block = path, 128 threads.
//   Phase 1: per-thread CG entry + per-thread Q-matrix entry (shared).
//   Phase 2: per-thread Cr[j,l,m] (125-term complex contraction).
//   Phase 3: Frobenius reduce, scale by sqrt(alpha), padded write.
// Identical fp64 math to the verified serial version (rel_err 4.56e-7).
// ---------------------------------------------------------------------------
__device__ __forceinline__ double dfact(int n) {
    double r = 1.0;
    for (int i = 2; i <= n; i++) r *= (double)i;
    return r;
}

__global__ void tp_init_w3() {
    const int p = blockIdx.x;      // 0..10
    const int t = threadIdx.x;     // 0..127
    const int l1 = c_l1[p], l2 = c_l2[p], l3 = c_lo[p];
    const int n1 = 2 * l1 + 1, n2 = 2 * l2 + 1, n3 = 2 * l3 + 1;
    const int nTot = n1 * n2 * n3;

    __shared__ double sC[125];           // CG, tight [n1][n2][n3]
    __shared__ double sQr[3][25], sQi[3][25];  // padded 5x5 per matrix
    __shared__ double sCr[125];
    __shared__ double sScale;

    // --- Phase 1a: SU(2) Clebsch-Gordan, one entry per thread ---
    if (t < nTot) {
        int a = t / (n2 * n3), rem = t % (n2 * n3), b = rem / n3, c = rem % n3;
        int m1 = a - l1, m2 = b - l2, m3 = c - l3;
        double v = 0.0;
        if (m1 + m2 == m3) {
            double pref = sqrt((double)(2 * l3 + 1) * dfact(l3 + l1 - l2) * dfact(l3 - l1 + l2) *
                               dfact(l1 + l2 - l3) / dfact(l1 + l2 + l3 + 1));
            pref *= sqrt(dfact(l3 + m3) * dfact(l3 - m3) * dfact(l1 - m1) * dfact(l1 + m1) *
                         dfact(l2 - m2) * dfact(l2 + m2));
            double s = 0.0;
            for (int k = 0; k <= l1 + l2 - l3; k++) {
                if (l1 - m1 - k < 0 || l2 + m2 - k < 0 ||
                    l3 - l2 + m1 + k < 0 || l3 - l1 - m2 + k < 0) continue;
                double term = 1.0 / (dfact(k) * dfact(l1 + l2 - l3 - k) * dfact(l1 - m1 - k) *
                                     dfact(l2 + m2 - k) * dfact(l3 - l2 + m1 + k) *
                                     dfact(l3 - l1 - m2 + k));
                s += (k & 1) ? -term : term;
            }
            v = pref * s;
        }
        sC[t] = v;
    }

    // --- Phase 1b: real-basis matrices q(l) = (-i)^l * base, one entry/thread
    // Entry (row r, col cc) of matrix mt in {Q1,Q2,Q3}:
    //   m = r - l:  m<0: col 2l-r -> 1/sqrt2,  col r -> -i/sqrt2
    //               m=0: col l -> 1
    //               m>0: col r -> (-1)^m/sqrt2, col 2l-r -> i(-1)^m/sqrt2
    if (t < 75) {
        int mt = t / 25, e = t % 25;
        int l = (mt == 0) ? l1 : (mt == 1) ? l2 : l3;
        int n = 2 * l + 1;
        int r = e / 5, cc = e % 5;
        double qr = 0.0, qi = 0.0;
        if (r < n && cc < n) {
            double inv = 1.0 / sqrt(2.0);
            int m = r - l;
            if (m < 0) {
                if (cc == 2 * l - r) qr = inv;       // col l+|m|
                if (cc == r)         qi = -inv;      // col l-|m|
            } else if (m == 0) {
                if (cc == l) qr = 1.0;
            } else {
                double sgn = (m & 1) ? -1.0 : 1.0;
                if (cc == r)         qr = sgn * inv; // col l+|m|
                if (cc == 2 * l - r) qi = sgn * inv; // col l-|m|
            }
            int ph = l & 3;  // multiply by (-i)^l
            double rr = qr, ii = qi;
            if (ph == 1)      { qr =  ii; qi = -rr; }
            else if (ph == 2) { qr = -rr; qi = -ii; }
            else if (ph == 3) { qr = -ii; qi =  rr; }
        }
        sQr[mt][e] = qr;
        sQi[mt][e] = qi;
    }
    __syncthreads();

    // --- Phase 2: Cr[j,l,m] = Re( sum_{i,k,n} Q1[i][j] Q2[k][l] conj(Q3[n][m]) C[i][k][n] )
    if (t < nTot) {
        int j = t / (n2 * n3), rem = t % (n2 * n3), lc = rem / n3, m = rem % n3;
        double re = 0.0;
        for (int i = 0; i < n1; i++) {
            double q1r = sQr[0][i * 5 + j], q1i = sQi[0][i * 5 + j];
            for (int k = 0; k < n2; k++) {
                double q2r = sQr[1][k * 5 + lc], q2i = sQi[1][k * 5 + lc];
                double t1r = q1r * q2r - q1i * q2i;
                double t1i = q1r * q2i + q1i * q2r;
                for (int n = 0; n < n3; n++) {
                    double c = sC[i * (n2 * n3) + k * n3 + n];
                    if (c == 0.0) continue;
                    double q3r = sQr[2][n * 5 + m], q3i = -sQi[2][n * 5 + m];  // conj
                    re += c * (t1r * q3r - t1i * q3i);
                }
            }
        }
        sCr[t] = re;
    }
    __syncthreads();

    // --- Phase 3: Frobenius norm + alpha scale ---
    if (t == 0) {
        double f = 0.0;
        for (int e = 0; e < nTot; e++) f += sCr[e] * sCr[e];
        double alpha = (l3 == 0) ? (1.0 / 384.0) : (l3 == 1) ? (3.0 / 512.0) : (5.0 / 512.0);
        sScale = sqrt(alpha) / sqrt(f);
    }
    __syncthreads();

    // padded write: g_W3[p*125 + j*25 + l*5 + m]
    if (t < 125) {
        int j = t / 25, rem = t % 25, lc = rem / 5, m = rem % 5;
        float v = 0.0f;
        if (j < n1 && lc < n2 && m < n3)
            v = (float)(sCr[j * (n2 * n3) + lc * n3 + m] * sScale);
        g_W3[p * 125 + t] = v;
    }
}

// ---------------------------------------------------------------------------
// Packed f32x2 FMA (SASS FFMA2 — only reachable via PTX).
// ---------------------------------------------------------------------------
__device__ __forceinline__ void fma2(u64& d, u64 a, u64 b) {
    asm("fma.rn.f32x2 %0, %1, %2, %0;" : "+l"(d) : "l"(a), "l"(b));
}

__device__ __forceinline__ float2 u2f(u64 v) {
    float2 r;
    r.x = __uint_as_float((unsigned)(v & 0xffffffffULL));
    r.y = __uint_as_float((unsigned)(v >> 32));
    return r;
}

// Split a (w, w+1) u64 into two lane-duplicated u64s: {w,w} and {w+1,w+1}.
__device__ __forceinline__ void dups(u64 v, u64& lo2, u64& hi2) {
    unsigned lo, hi;
    asm("mov.b64 {%0,%1}, %2;" : "=r"(lo), "=r"(hi) : "l"(v));
    asm("mov.b64 %0, {%1,%1};" : "=l"(lo2) : "r"(lo));
    asm("mov.b64 %0, {%1,%1};" : "=l"(hi2) : "r"(hi));
}

// ---------------------------------------------------------------------------
// Staging: one path, compile-time geometry; writes one f32 lane of the
// interleaved (b_even, b_odd) float2 A-row.
// ---------------------------------------------------------------------------
template <int L1V, int LOV, int S1, int GOFF, int AOFF>
__device__ __forceinline__ void stage_path(const float* __restrict__ x1b,
                                           const float* __restrict__ gb,
                                           float* __restrict__ ArowF,
                                           int lane, int u) {
    constexpr int nI = 2 * L1V + 1, nK = 2 * LOV + 1;
    float xv[nI];
#pragma unroll
    for (int i = 0; i < nI; i++) xv[i] = x1b[S1 + u * nI + i];
#pragma unroll
    for (int k = 0; k < nK; k++) {
        float s = 0.0f;
#pragma unroll
        for (int i = 0; i < nI; i++) s = fmaf(xv[i], gb[GOFF + i * nK + k], s);
        ArowF[(AOFF + k) * 2 + lane] = s;
    }
}

// ---------------------------------------------------------------------------
// Hot-loop regions. acc[wi][pair][slot]; wrow = &ws_u64[u*64 + wp].
// ---------------------------------------------------------------------------

// Two NK=5 paths (10 consecutive c at ull2 offset C2), both into slots S0..S0+4.
template <int PA, int PB, int C2, int S0>
__device__ __forceinline__ void region10(const u64* __restrict__ wrow,
                                         const ulonglong2* __restrict__ A0r,
                                         const ulonglong2* __restrict__ A1r,
                                         u64 (&acc)[2][2][9]) {
    u64 wa = wrow[PA * 8192], wb = wrow[PB * 8192];
    u64 wa0, wa1, wb0, wb1;
    dups(wa, wa0, wa1);
    dups(wb, wb0, wb1);
#pragma unroll
    for (int pr = 0; pr < 2; pr++) {
        const ulonglong2* Ar = pr ? A1r : A0r;
        ulonglong2 x0 = Ar[C2], x1 = Ar[C2 + 1], x2 = Ar[C2 + 2],
                   x3 = Ar[C2 + 3], x4 = Ar[C2 + 4];
        fma2(acc[0][pr][S0 + 0], x0.x, wa0); fma2(acc[1][pr][S0 + 0], x0.x, wa1);
        fma2(acc[0][pr][S0 + 1], x0.y, wa0); fma2(acc[1][pr][S0 + 1], x0.y, wa1);
        fma2(acc[0][pr][S0 + 2], x1.x, wa0); fma2(acc[1][pr][S0 + 2], x1.x, wa1);
        fma2(acc[0][pr][S0 + 3], x1.y, wa0); fma2(acc[1][pr][S0 + 3], x1.y, wa1);
        fma2(acc[0][pr][S0 + 4], x2.x, wa0); fma2(acc[1][pr][S0 + 4], x2.x, wa1);
        fma2(acc[0][pr][S0 + 0], x2.y, wb0); fma2(acc[1][pr][S0 + 0], x2.y, wb1);
        fma2(acc[0][pr][S0 + 1], x3.x, wb0); fma2(acc[1][pr][S0 + 1], x3.x, wb1);
        fma2(acc[0][pr][S0 + 2], x3.y, wb0); fma2(acc[1][pr][S0 + 2], x3.y, wb1);
        fma2(acc[0][pr][S0 + 3], x4.x, wb0); fma2(acc[1][pr][S0 + 3], x4.x, wb1);
        fma2(acc[0][pr][S0 + 4], x4.y, wb0); fma2(acc[1][pr][S0 + 4], x4.y, wb1);
    }
}

// Two NK=3 paths (6 consecutive c at ull2 offset C2), both into slots S0..S0+2.
template <int PA, int PB, int C2, int S0>
__device__ __forceinline__ void region6(const u64* __restrict__ wrow,
                                        const ulonglong2* __restrict__ A0r,
                                        const ulonglong2* __restrict__ A1r,
                                        u64 (&acc)[2][2][9]) {
    u64 wa = wrow[PA * 8192], wb = wrow[PB * 8192];
    u64 wa0, wa1, wb0, wb1;
    dups(wa, wa0, wa1);
    dups(wb, wb0, wb1);
#pragma unroll
    for (int pr = 0; pr < 2; pr++) {
        const ulonglong2* Ar = pr ? A1r : A0r;
        ulonglong2 x0 = Ar[C2], x1 = Ar[C2 + 1], x2 = Ar[C2 + 2];
        fma2(acc[0][pr][S0 + 0], x0.x, wa0); fma2(acc[1][pr][S0 + 0], x0.x, wa1);
        fma2(acc[0][pr][S0 + 1], x0.y, wa0); fma2(acc[1][pr][S0 + 1], x0.y, wa1);
        fma2(acc[0][pr][S0 + 2], x1.x, wa0); fma2(acc[1][pr][S0 + 2], x1.x, wa1);
        fma2(acc[0][pr][S0 + 0], x1.y, wb0); fma2(acc[1][pr][S0 + 0], x1.y, wb1);
        fma2(acc[0][pr][S0 + 1], x2.x, wb0); fma2(acc[1][pr][S0 + 1], x2.x, wb1);
        fma2(acc[0][pr][S0 + 2], x2.y, wb0); fma2(acc[1][pr][S0 + 2], x2.y, wb1);
    }
}

// Three NK=1 paths (c at ull2 offset C2: x.x=PA, x.y=PB; u64 at float2 idx CF=PC),
// all into slot S0.
template <int PA, int PB, int PC, int C2, int CF, int S0>
__device__ __forceinline__ void region3(const u64* __restrict__ wrow,
                                        const ulonglong2* __restrict__ A0r,
                                        const ulonglong2* __restrict__ A1r,
                                        u64 (&acc)[2][2][9]) {
    u64 wa = wrow[PA * 8192], wb = wrow[PB * 8192], wc = wrow[PC * 8192];
    u64 wa0, wa1, wb0, wb1, wc0, wc1;
    dups(wa, wa0, wa1);
    dups(wb, wb0, wb1);
    dups(wc, wc0, wc1);
#pragma unroll
    for (int pr = 0; pr < 2; pr++) {
        const ulonglong2* Ar = pr ? A1r : A0r;
        ulonglong2 x0 = Ar[C2];
        u64 x2 = reinterpret_cast<const u64*>(Ar)[CF];
        fma2(acc[0][pr][S0], x0.x, wa0); fma2(acc[1][pr][S0], x0.x, wa1);
        fma2(acc[0][pr][S0], x0.y, wb0); fma2(acc[1][pr][S0], x0.y, wb1);
        fma2(acc[0][pr][S0], x2,   wc0); fma2(acc[1][pr][S0], x2,   wc1);
    }
}

// ---------------------------------------------------------------------------
// Main kernel (unchanged from R11). Block: 16 batches (8 pairs), 8 warps.
//   warp = wg*2 + wh: wg = pair-group (owns pairs 2wg, 2wg+1 = batches 4wg..4wg+3)
//                     wh = w-half; thread w-pair wp = wh*32 + lane; w = 2wp+wi.
// acc[2 wi][2 pair][9 slot] u64 = 72 regs. 2 CTAs/SM (regs <= 128, smem 44.5KB).
// ---------------------------------------------------------------------------
__global__ void __launch_bounds__(NTHREADS, 2)
tp_main(const float* __restrict__ x1, const float* __restrict__ x2,
        const float* __restrict__ ws, float* __restrict__ out) {
    extern __shared__ float smem[];
    float* sG = smem;                                          // TB*120 floats
    float2* sA = reinterpret_cast<float2*>(smem + TB * 120);   // 8 pairs * KC * ASTR

    const int tid = threadIdx.x;
    const int b0 = blockIdx.x * TB;

    // ---- G_p[i][k] = sum_j W3s[p][i][j][k] * x2[b][s2off[l2]+j] ----
    if (tid < TB * 11) {
        int b = tid / 11, p = tid % 11;
        int l1 = c_l1[p], l2 = c_l2[p], lo = c_lo[p], goff = c_goff[p];
        int nI = 2 * l1 + 1, nJ = 2 * l2 + 1, nK = 2 * lo + 1;
        const float* w3 = g_W3 + p * 125;
        const float* x2b = x2 + (size_t)(b0 + b) * 9 + c_s2off[l2];
        float* G = sG + b * 120 + goff;
        for (int i = 0; i < nI; i++)
            for (int k = 0; k < nK; k++) {
                float s = 0.0f;
                for (int j = 0; j < nJ; j++)
                    s = fmaf(w3[i * 25 + j * 5 + k], x2b[j], s);
                G[i * nK + k] = s;
            }
    }
    __syncthreads();

    const int warp = tid >> 5;
    const int lane = tid & 31;
    const int wg = warp >> 1;          // pair-group 0..3
    const int wh = warp & 1;           // w-half
    const int wp = wh * 32 + lane;     // w-pair 0..63; w = 2wp, 2wp+1
    const u64* wsv = reinterpret_cast<const u64*>(ws);

    u64 acc[2][2][9];
#pragma unroll
    for (int wi = 0; wi < 2; wi++)
#pragma unroll
        for (int pr = 0; pr < 2; pr++)
#pragma unroll
            for (int s = 0; s < 9; s++) acc[wi][pr][s] = 0ULL;

    // staging job: (b, ul) = (tid>>4, tid&15); writes lane b&1 of pair b>>1
    const int sb = tid >> 4;
    const int sul = tid & 15;
    const int sln = sb & 1;
    const float* x1b = x1 + (size_t)(b0 + sb) * 1152;
    const float* gb = sG + sb * 120;
    float* ArowF = reinterpret_cast<float*>(sA + ((sb >> 1) * KC + sul) * ASTR);

    const int pA = 2 * wg, pB = 2 * wg + 1;   // consumption pair rows

    for (int uc = 0; uc < 128; uc += KC) {
        // ---- stage A[pair][u][c] interleaved (b_even, b_odd) ----
        {
            int u = uc + sul;
            // p: <l1, lo, s1off, goff, aoff(c-index)>
            stage_path<0, 2,   0,  4,  0>(x1b, gb, ArowF, sln, u);   // p2
            stage_path<1, 2, 128, 21,  5>(x1b, gb, ArowF, sln, u);   // p5
            stage_path<2, 2, 512, 45, 10>(x1b, gb, ArowF, sln, u);   // p7
            stage_path<2, 2, 512, 90, 15>(x1b, gb, ArowF, sln, u);   // p10
            stage_path<0, 1,   0,  1, 20>(x1b, gb, ArowF, sln, u);   // p1
            stage_path<1, 1, 128,  9, 23>(x1b, gb, ArowF, sln, u);   // p3
            stage_path<1, 1, 128, 36, 26>(x1b, gb, ArowF, sln, u);   // p6
            stage_path<2, 1, 512, 70, 29>(x1b, gb, ArowF, sln, u);   // p8
            stage_path<0, 0,   0,  0, 32>(x1b, gb, ArowF, sln, u);   // p0
            stage_path<1, 0, 128, 18, 33>(x1b, gb, ArowF, sln, u);   // p4
            stage_path<2, 0, 512, 85, 34>(x1b, gb, ArowF, sln, u);   // p9
        }
        __syncthreads();

        // ---- heavy contraction over this u-chunk (FFMA2-bound) ----
#pragma unroll 1
        for (int ul = 0; ul < KC; ul++) {
            const u64* wrow = wsv + (size_t)(uc + ul) * 64 + wp;
            const ulonglong2* A0r =
                reinterpret_cast<const ulonglong2*>(sA + (pA * KC + ul) * ASTR);
            const ulonglong2* A1r =
                reinterpret_cast<const ulonglong2*>(sA + (pB * KC + ul) * ASTR);
            region10<2, 5,  0, 4>(wrow, A0r, A1r, acc);   // p2,p5  -> l2 slots
            region10<7, 10, 5, 4>(wrow, A0r, A1r, acc);   // p7,p10 -> l2 slots
            region6 <1, 3, 10, 1>(wrow, A0r, A1r, acc);   // p1,p3  -> l1 slots
            region6 <6, 8, 13, 1>(wrow, A0r, A1r, acc);   // p6,p8  -> l1 slots
            region3 <0, 4, 9, 16, 34, 0>(wrow, A0r, A1r, acc);  // p0,p4,p9 -> l0
        }
        __syncthreads();   // sA about to be overwritten
    }

    // ---- write out: lanes = (b_even, b_odd) of pair; slots -> segments ----
#pragma unroll
    for (int pr = 0; pr < 2; pr++) {
#pragma unroll
        for (int wi = 0; wi < 2; wi++) {
            int w = 2 * wp + wi;
#pragma unroll
            for (int s = 0; s < 9; s++) {
                float2 v = u2f(acc[wi][pr][s]);
                size_t baseE = (size_t)(b0 + 4 * wg + 2 * pr) * 1152;
                size_t baseO = baseE + 1152;
                int off;
                if (s == 0)      off = w;
                else if (s < 4)  off = 128 + w * 3 + (s - 1);
                else             off = 512 + w * 5 + (s - 4);
                out[baseE + off] = v.x;
                out[baseO + off] = v.y;
            }
        }
    }
}

// ---------------------------------------------------------------------------
extern "C" void kernel_launch(void* const* d_in, const int* in_sizes, int n_in,
                              void* d_out, int out_size) {
    const float* x1 = (const float*)d_in[0];
    const float* x2 = (const float*)d_in[1];
    const float* ws = (const float*)d_in[2];
    float* out = (float*)d_out;

    int B = in_sizes[0] / 1152;              // 32768
    int grid = B / TB;                       // 2048

    const int smem_bytes = TB * 120 * 4 + (TB / 2) * KC * ASTR * 8;  // 7680+36864=44544
    cudaFuncSetAttribute(tp_main, cudaFuncAttributeMaxDynamicSharedMemorySize, smem_bytes);

    tp_init_w3<<<11, 128>>>();
    tp_main<<<grid, NTHREADS, smem_bytes>>>(x1, x2, ws, out);
}